// round 7
// baseline (speedup 1.0000x reference)
#include <cuda_runtime.h>
#include <cstdint>

#define N_NODES 40000
#define N_EDGES 640000
#define D 128
#define N_OPS 5
#define EPS 1e-5f
#define STAT_BLOCKS 160
#define FLT_BIG 3.402823466e38f

// ---------------- scratch (static device globals; no runtime allocation) ---
__device__ int   g_is32;              // 1 if edge_index is int32, 0 if int64
__device__ int   g_deg[N_NODES];
__device__ int   g_offs[N_NODES + 1];
__device__ int   g_cursor[N_NODES];
__device__ int   g_csr_src[N_EDGES];
__device__ float g_sum[(size_t)N_NODES * D];
__device__ float g_max[(size_t)N_NODES * D];
__device__ float g_part[(size_t)STAT_BLOCKS * 2 * N_OPS * D];  // [blk][sum/sq][b][d]
__device__ float g_A[N_OPS * D];
__device__ float g_C[N_OPS * D];

// ---------------- 0. detect edge_index dtype (int32 vs int64) -------------
// If the buffer is int32, an int64 view packs two random indices per word, so
// values fall outside [0, N_NODES) with overwhelming probability within 256
// samples (256*8 bytes is within the buffer under both interpretations).
__global__ void k_detect(const long long* __restrict__ ei) {
    if (threadIdx.x == 0 && blockIdx.x == 0) {
        int is32 = 0;
        for (int i = 0; i < 256; i++) {
            long long v = ei[i];
            if (v < 0 || v >= N_NODES) { is32 = 1; break; }
        }
        g_is32 = is32;
    }
}

__device__ __forceinline__ int load_idx(const void* ei, int pos, int is32) {
    if (is32) return ((const int*)ei)[pos];
    return (int)((const long long*)ei)[pos];
}

// ---------------- 1. zero the degree histogram (graph must be idempotent) --
__global__ void k_zero_deg() {
    int i = blockIdx.x * blockDim.x + threadIdx.x;
    if (i < N_NODES) g_deg[i] = 0;
}

// ---------------- 2. degree histogram -------------------------------------
__global__ void k_hist(const void* __restrict__ ei) {
    int e = blockIdx.x * blockDim.x + threadIdx.x;
    if (e < N_EDGES) {
        int dst = load_idx(ei, N_EDGES + e, g_is32);
        if ((unsigned)dst < N_NODES) atomicAdd(&g_deg[dst], 1);
    }
}

// ---------------- 3. exclusive scan of degrees (single 1024-thread block) --
__global__ void k_scan() {
    const int IPT = 40;  // 1024*40 = 40960 >= N_NODES
    int tid  = threadIdx.x;
    int lane = tid & 31, wid = tid >> 5;
    int base = tid * IPT;

    int s = 0;
    #pragma unroll
    for (int i = 0; i < IPT; i++) {
        int idx = base + i;
        s += (idx < N_NODES) ? g_deg[idx] : 0;
    }

    __shared__ int wsum[32];
    int v = s;
    #pragma unroll
    for (int off = 1; off < 32; off <<= 1) {
        int t = __shfl_up_sync(0xffffffffu, v, off);
        if (lane >= off) v += t;
    }
    if (lane == 31) wsum[wid] = v;
    __syncthreads();
    if (wid == 0) {
        int w = wsum[lane];
        #pragma unroll
        for (int off = 1; off < 32; off <<= 1) {
            int t = __shfl_up_sync(0xffffffffu, w, off);
            if (lane >= off) w += t;
        }
        wsum[lane] = w;  // inclusive scan of warp totals
    }
    __syncthreads();

    int pref = (v - s) + (wid ? wsum[wid - 1] : 0);  // block-exclusive prefix
    int run = pref;
    #pragma unroll
    for (int i = 0; i < IPT; i++) {
        int idx = base + i;
        if (idx < N_NODES) {
            g_offs[idx]   = run;
            g_cursor[idx] = run;
            run += g_deg[idx];
        }
    }
    if (tid == 0) g_offs[N_NODES] = wsum[31];
}

// ---------------- 4. fill CSR source lists --------------------------------
__global__ void k_fill(const void* __restrict__ ei) {
    int e = blockIdx.x * blockDim.x + threadIdx.x;
    if (e < N_EDGES) {
        int is32 = g_is32;
        int src = load_idx(ei, e, is32);
        int dst = load_idx(ei, N_EDGES + e, is32);
        if ((unsigned)dst < N_NODES && (unsigned)src < N_NODES) {
            int pos = atomicAdd(&g_cursor[dst], 1);
            g_csr_src[pos] = src;
        }
    }
}

// ---------------- 5. per-node warp aggregation (sum + max), no atomics ----
// Dual-edge unroll: two independent LDG.128 per lane in flight (MLP=2) to
// cover L2-hit latency (~230-260 cyc) on the 327 MB gather stream.
__global__ void k_agg(const float* __restrict__ h) {
    int warp = (blockIdx.x * blockDim.x + threadIdx.x) >> 5;
    int lane = threadIdx.x & 31;
    if (warp >= N_NODES) return;

    int start = g_offs[warp];
    int end   = g_offs[warp + 1];

    float4 s0 = make_float4(0.f, 0.f, 0.f, 0.f);
    float4 s1 = make_float4(0.f, 0.f, 0.f, 0.f);
    float4 m0 = make_float4(-FLT_BIG, -FLT_BIG, -FLT_BIG, -FLT_BIG);
    float4 m1 = make_float4(-FLT_BIG, -FLT_BIG, -FLT_BIG, -FLT_BIG);

    const float* hp = h + lane * 4;

    for (int b = start; b < end; b += 32) {
        int idx = b + lane;
        int sv  = (idx < end) ? g_csr_src[idx] : 0;
        int cnt = min(32, end - b);
        int k = 0;
        for (; k + 2 <= cnt; k += 2) {
            int sa = __shfl_sync(0xffffffffu, sv, k);
            int sb = __shfl_sync(0xffffffffu, sv, k + 1);
            const float4 va = *reinterpret_cast<const float4*>(hp + (size_t)sa * D);
            const float4 vb = *reinterpret_cast<const float4*>(hp + (size_t)sb * D);
            s0.x += va.x; s0.y += va.y; s0.z += va.z; s0.w += va.w;
            m0.x = fmaxf(m0.x, va.x); m0.y = fmaxf(m0.y, va.y);
            m0.z = fmaxf(m0.z, va.z); m0.w = fmaxf(m0.w, va.w);
            s1.x += vb.x; s1.y += vb.y; s1.z += vb.z; s1.w += vb.w;
            m1.x = fmaxf(m1.x, vb.x); m1.y = fmaxf(m1.y, vb.y);
            m1.z = fmaxf(m1.z, vb.z); m1.w = fmaxf(m1.w, vb.w);
        }
        if (k < cnt) {
            int sa = __shfl_sync(0xffffffffu, sv, k);
            const float4 va = *reinterpret_cast<const float4*>(hp + (size_t)sa * D);
            s0.x += va.x; s0.y += va.y; s0.z += va.z; s0.w += va.w;
            m0.x = fmaxf(m0.x, va.x); m0.y = fmaxf(m0.y, va.y);
            m0.z = fmaxf(m0.z, va.z); m0.w = fmaxf(m0.w, va.w);
        }
    }

    float4 s = make_float4(s0.x + s1.x, s0.y + s1.y, s0.z + s1.z, s0.w + s1.w);
    float4 m = make_float4(fmaxf(m0.x, m1.x), fmaxf(m0.y, m1.y),
                           fmaxf(m0.z, m1.z), fmaxf(m0.w, m1.w));
    if (end == start) m = make_float4(0.f, 0.f, 0.f, 0.f);  // empty segment -> 0

    size_t o = (size_t)warp * D + lane * 4;
    *reinterpret_cast<float4*>(g_sum + o) = s;
    *reinterpret_cast<float4*>(g_max + o) = m;
}

// ---------------- 6. per-block BN partial sums (deterministic) ------------
__global__ void k_stats(const float* __restrict__ h, const float* __restrict__ hin) {
    int d   = threadIdx.x;           // 0..127
    int blk = blockIdx.x;            // 0..STAT_BLOCKS-1
    const int chunk = (N_NODES + STAT_BLOCKS - 1) / STAT_BLOCKS;  // 250
    int n0 = blk * chunk;
    int n1 = min(N_NODES, n0 + chunk);

    float s[N_OPS] = {0, 0, 0, 0, 0};
    float q[N_OPS] = {0, 0, 0, 0, 0};
    for (int n = n0; n < n1; n++) {
        size_t o = (size_t)n * D + d;
        float x0 = h[o];
        float x1 = hin[o];
        float x2 = g_sum[o];
        float inv = 1.0f / fmaxf((float)g_deg[n], 1.0f);
        float x3 = x2 * inv;
        float x4 = g_max[o];
        s[0] += x0; q[0] += x0 * x0;
        s[1] += x1; q[1] += x1 * x1;
        s[2] += x2; q[2] += x2 * x2;
        s[3] += x3; q[3] += x3 * x3;
        s[4] += x4; q[4] += x4 * x4;
    }
    size_t base = (size_t)blk * 2 * N_OPS * D;
    #pragma unroll
    for (int b = 0; b < N_OPS; b++) {
        g_part[base + b * D + d]           = s[b];
        g_part[base + (N_OPS + b) * D + d] = q[b];
    }
}

// ---------------- 7. reduce partials -> fused BN coefficients -------------
__global__ void k_coef(const float* __restrict__ w,
                       const float* __restrict__ gamma,
                       const float* __restrict__ beta) {
    int t = blockIdx.x * blockDim.x + threadIdx.x;  // (b,d) flat
    if (t >= N_OPS * D) return;
    int b = t / D;
    float S = 0.f, Q = 0.f;
    for (int g = 0; g < STAT_BLOCKS; g++) {
        size_t base = (size_t)g * 2 * N_OPS * D;
        S += g_part[base + t];
        Q += g_part[base + N_OPS * D + t];
    }
    float mu   = S * (1.0f / N_NODES);
    float var  = fmaxf(Q * (1.0f / N_NODES) - mu * mu, 0.0f);
    float rstd = rsqrtf(var + EPS);
    float A = w[b] * gamma[t] * rstd;   // weights >= 0, fold inside ReLU
    float C = w[b] * beta[t] - A * mu;
    g_A[t] = A;
    g_C[t] = C;
}

// ---------------- 8. fused normalize + ReLU + weighted sum ----------------
__global__ void k_final(const float* __restrict__ h, const float* __restrict__ hin,
                        float* __restrict__ out) {
    __shared__ float sA[N_OPS * D];
    __shared__ float sC[N_OPS * D];
    for (int i = threadIdx.x; i < N_OPS * D; i += blockDim.x) {
        sA[i] = g_A[i];
        sC[i] = g_C[i];
    }
    __syncthreads();

    int gid = blockIdx.x * blockDim.x + threadIdx.x;  // one float4 per thread
    if (gid >= N_NODES * (D / 4)) return;
    int n  = gid >> 5;
    int f4 = (gid & 31) * 4;
    size_t o = (size_t)n * D + f4;

    float4 x0 = *reinterpret_cast<const float4*>(h + o);
    float4 x1 = *reinterpret_cast<const float4*>(hin + o);
    float4 x2 = *reinterpret_cast<const float4*>(g_sum + o);
    float4 x4 = *reinterpret_cast<const float4*>(g_max + o);
    float inv = 1.0f / fmaxf((float)g_deg[n], 1.0f);
    float4 x3 = make_float4(x2.x * inv, x2.y * inv, x2.z * inv, x2.w * inv);

    float xs[N_OPS][4] = {
        {x0.x, x0.y, x0.z, x0.w},
        {x1.x, x1.y, x1.z, x1.w},
        {x2.x, x2.y, x2.z, x2.w},
        {x3.x, x3.y, x3.z, x3.w},
        {x4.x, x4.y, x4.z, x4.w},
    };
    float acc[4] = {0.f, 0.f, 0.f, 0.f};
    #pragma unroll
    for (int b = 0; b < N_OPS; b++) {
        #pragma unroll
        for (int c = 0; c < 4; c++) {
            float A = sA[b * D + f4 + c];
            float C = sC[b * D + f4 + c];
            acc[c] += fmaxf(fmaf(A, xs[b][c], C), 0.0f);
        }
    }
    *reinterpret_cast<float4*>(out + o) = make_float4(acc[0], acc[1], acc[2], acc[3]);
}

// ---------------- launch ---------------------------------------------------
extern "C" void kernel_launch(void* const* d_in, const int* in_sizes, int n_in,
                              void* d_out, int out_size) {
    const float* weights = (const float*)d_in[0];
    const void*  ei      = d_in[1];                 // int32 or int64, detected on-device
    const float* h       = (const float*)d_in[2];
    const float* hin     = (const float*)d_in[3];
    const float* gamma   = (const float*)d_in[4];
    const float* beta    = (const float*)d_in[5];
    float*       out     = (float*)d_out;

    k_detect<<<1, 32>>>((const long long*)ei);
    k_zero_deg<<<(N_NODES + 255) / 256, 256>>>();
    k_hist<<<(N_EDGES + 255) / 256, 256>>>(ei);
    k_scan<<<1, 1024>>>();
    k_fill<<<(N_EDGES + 255) / 256, 256>>>(ei);
    k_agg<<<(N_NODES * 32 + 255) / 256, 256>>>(h);
    k_stats<<<STAT_BLOCKS, D>>>(h, hin);
    k_coef<<<(N_OPS * D + 255) / 256, 256>>>(weights, gamma, beta);
    k_final<<<(N_NODES * (D / 4) + 255) / 256, 256>>>(h, hin, out);
}

// round 8
// speedup vs baseline: 1.6670x; 1.6670x over previous
#include <cuda_runtime.h>
#include <cstdint>

#define N_NODES 40000
#define N_EDGES 640000
#define D 128
#define N_OPS 5
#define EPS 1e-5f
#define STAT_BLOCKS 320
#define FLT_BIG 3.402823466e38f
#define SCAN_BLOCKS 40
#define SCAN_CHUNK 1000          // SCAN_BLOCKS * SCAN_CHUNK == N_NODES

// ---------------- scratch (static device globals; no runtime allocation) ---
__device__ int   g_is32;              // 1 if edge_index is int32, 0 if int64
__device__ int   g_deg[N_NODES];
__device__ int   g_offs[N_NODES + 1];
__device__ int   g_cursor[N_NODES];
__device__ int   g_csr_src[N_EDGES];
__device__ int   g_bsum[SCAN_BLOCKS];
__device__ int   g_boff[SCAN_BLOCKS];
__device__ float g_sum[(size_t)N_NODES * D];
__device__ float g_max[(size_t)N_NODES * D];
__device__ float g_part[(size_t)STAT_BLOCKS * 2 * N_OPS * D];  // [blk][sum/sq][b][d]
__device__ float g_A[N_OPS * D];
__device__ float g_C[N_OPS * D];

// ---------------- 0. detect edge_index dtype (int32 vs int64) -------------
// int32 data viewed as int64 packs two random indices per word -> values fall
// outside [0, N_NODES) with overwhelming probability within 256 samples.
// Warp-parallel, no early-break dependent chain (batched loads).
__global__ void k_detect(const long long* __restrict__ ei) {
    int lane = threadIdx.x;  // 32 threads
    int bad = 0;
    #pragma unroll
    for (int i = 0; i < 8; i++) {
        long long v = ei[lane * 8 + i];
        bad |= (v < 0 || v >= N_NODES) ? 1 : 0;
    }
    unsigned m = __ballot_sync(0xffffffffu, bad);
    if (lane == 0) g_is32 = (m != 0u) ? 1 : 0;
}

__device__ __forceinline__ int load_idx(const void* ei, int pos, int is32) {
    if (is32) return ((const int*)ei)[pos];
    return (int)((const long long*)ei)[pos];
}

// ---------------- 1. zero the degree histogram (graph must be idempotent) --
__global__ void k_zero_deg() {
    int i = blockIdx.x * blockDim.x + threadIdx.x;
    if (i < N_NODES) g_deg[i] = 0;
}

// ---------------- 2. degree histogram -------------------------------------
__global__ void k_hist(const void* __restrict__ ei) {
    int e = blockIdx.x * blockDim.x + threadIdx.x;
    if (e < N_EDGES) {
        int dst = load_idx(ei, N_EDGES + e, g_is32);
        if ((unsigned)dst < N_NODES) atomicAdd(&g_deg[dst], 1);
    }
}

// ---------------- 3a. per-chunk degree sums (coalesced, chip-wide) --------
__global__ void k_chunksum() {
    __shared__ int red[8];
    int b = blockIdx.x, tid = threadIdx.x;  // 256 threads
    int base = b * SCAN_CHUNK;
    int s = 0;
    for (int i = tid; i < SCAN_CHUNK; i += 256) s += g_deg[base + i];
    #pragma unroll
    for (int o = 16; o; o >>= 1) s += __shfl_down_sync(0xffffffffu, s, o);
    if ((tid & 31) == 0) red[tid >> 5] = s;
    __syncthreads();
    if (tid == 0) {
        int v = 0;
        #pragma unroll
        for (int i = 0; i < 8; i++) v += red[i];
        g_bsum[b] = v;
    }
}

// ---------------- 3b. exclusive scan of 40 chunk sums ---------------------
__global__ void k_bscan() {
    __shared__ int sm[SCAN_BLOCKS];
    int tid = threadIdx.x;  // 64 threads
    if (tid < SCAN_BLOCKS) sm[tid] = g_bsum[tid];
    __syncthreads();
    if (tid == 0) {
        int run = 0;
        #pragma unroll
        for (int i = 0; i < SCAN_BLOCKS; i++) { int d = sm[i]; sm[i] = run; run += d; }
        g_offs[N_NODES] = run;
    }
    __syncthreads();
    if (tid < SCAN_BLOCKS) g_boff[tid] = sm[tid];
}

// ---------------- 3c. apply: in-chunk exclusive scan (smem-staged) --------
__global__ void k_apply() {
    __shared__ int sdeg[SCAN_CHUNK];
    __shared__ int wtot[8];
    int b = blockIdx.x, tid = threadIdx.x;  // 256 threads
    int lane = tid & 31, wid = tid >> 5;
    int base = b * SCAN_CHUNK;

    for (int i = tid; i < SCAN_CHUNK; i += 256) sdeg[i] = g_deg[base + i];
    __syncthreads();

    const int PT = 4;                      // 250 threads x 4 = 1000
    int i0 = tid * PT;
    int s = 0;
    if (i0 < SCAN_CHUNK) {
        #pragma unroll
        for (int i = 0; i < PT; i++) s += sdeg[i0 + i];
    }
    // warp-inclusive scan of per-thread sums
    int v = s;
    #pragma unroll
    for (int o = 1; o < 32; o <<= 1) {
        int t = __shfl_up_sync(0xffffffffu, v, o);
        if (lane >= o) v += t;
    }
    if (lane == 31) wtot[wid] = v;
    __syncthreads();
    __shared__ int wexc[8];
    if (tid == 0) {
        int run = 0;
        #pragma unroll
        for (int i = 0; i < 8; i++) { int d = wtot[i]; wexc[i] = run; run += d; }
    }
    __syncthreads();

    if (i0 < SCAN_CHUNK) {
        int run = g_boff[b] + wexc[wid] + (v - s);  // exclusive prefix for i0
        #pragma unroll
        for (int i = 0; i < PT; i++) {
            int idx = base + i0 + i;
            g_offs[idx]   = run;
            g_cursor[idx] = run;
            run += sdeg[i0 + i];
        }
    }
}

// ---------------- 4. fill CSR source lists --------------------------------
__global__ void k_fill(const void* __restrict__ ei) {
    int e = blockIdx.x * blockDim.x + threadIdx.x;
    if (e < N_EDGES) {
        int is32 = g_is32;
        int src = load_idx(ei, e, is32);
        int dst = load_idx(ei, N_EDGES + e, is32);
        if ((unsigned)dst < N_NODES && (unsigned)src < N_NODES) {
            int pos = atomicAdd(&g_cursor[dst], 1);
            g_csr_src[pos] = src;
        }
    }
}

// ---------------- 5. per-node warp aggregation (sum + max), no atomics ----
// 4-wide edge unroll: four independent LDG.128 per lane in flight (MLP=4) to
// cover L2-hit latency (~230-260 cyc) on the 327 MB gather stream.
__global__ void k_agg(const float* __restrict__ h) {
    int warp = (blockIdx.x * blockDim.x + threadIdx.x) >> 5;
    int lane = threadIdx.x & 31;
    if (warp >= N_NODES) return;

    int start = g_offs[warp];
    int end   = g_offs[warp + 1];

    float4 s0 = make_float4(0.f, 0.f, 0.f, 0.f), s1 = s0, s2 = s0, s3 = s0;
    float4 m0 = make_float4(-FLT_BIG, -FLT_BIG, -FLT_BIG, -FLT_BIG);
    float4 m1 = m0, m2 = m0, m3 = m0;

    const float* hp = h + lane * 4;

    for (int b = start; b < end; b += 32) {
        int idx = b + lane;
        int sv  = (idx < end) ? g_csr_src[idx] : 0;
        int cnt = min(32, end - b);
        int k = 0;
        for (; k + 4 <= cnt; k += 4) {
            int sa = __shfl_sync(0xffffffffu, sv, k);
            int sb = __shfl_sync(0xffffffffu, sv, k + 1);
            int sc = __shfl_sync(0xffffffffu, sv, k + 2);
            int sd = __shfl_sync(0xffffffffu, sv, k + 3);
            const float4 va = *reinterpret_cast<const float4*>(hp + (size_t)sa * D);
            const float4 vb = *reinterpret_cast<const float4*>(hp + (size_t)sb * D);
            const float4 vc = *reinterpret_cast<const float4*>(hp + (size_t)sc * D);
            const float4 vd = *reinterpret_cast<const float4*>(hp + (size_t)sd * D);
            s0.x += va.x; s0.y += va.y; s0.z += va.z; s0.w += va.w;
            m0.x = fmaxf(m0.x, va.x); m0.y = fmaxf(m0.y, va.y);
            m0.z = fmaxf(m0.z, va.z); m0.w = fmaxf(m0.w, va.w);
            s1.x += vb.x; s1.y += vb.y; s1.z += vb.z; s1.w += vb.w;
            m1.x = fmaxf(m1.x, vb.x); m1.y = fmaxf(m1.y, vb.y);
            m1.z = fmaxf(m1.z, vb.z); m1.w = fmaxf(m1.w, vb.w);
            s2.x += vc.x; s2.y += vc.y; s2.z += vc.z; s2.w += vc.w;
            m2.x = fmaxf(m2.x, vc.x); m2.y = fmaxf(m2.y, vc.y);
            m2.z = fmaxf(m2.z, vc.z); m2.w = fmaxf(m2.w, vc.w);
            s3.x += vd.x; s3.y += vd.y; s3.z += vd.z; s3.w += vd.w;
            m3.x = fmaxf(m3.x, vd.x); m3.y = fmaxf(m3.y, vd.y);
            m3.z = fmaxf(m3.z, vd.z); m3.w = fmaxf(m3.w, vd.w);
        }
        for (; k < cnt; k++) {
            int sa = __shfl_sync(0xffffffffu, sv, k);
            const float4 va = *reinterpret_cast<const float4*>(hp + (size_t)sa * D);
            s0.x += va.x; s0.y += va.y; s0.z += va.z; s0.w += va.w;
            m0.x = fmaxf(m0.x, va.x); m0.y = fmaxf(m0.y, va.y);
            m0.z = fmaxf(m0.z, va.z); m0.w = fmaxf(m0.w, va.w);
        }
    }

    float4 s = make_float4(s0.x + s1.x + s2.x + s3.x, s0.y + s1.y + s2.y + s3.y,
                           s0.z + s1.z + s2.z + s3.z, s0.w + s1.w + s2.w + s3.w);
    float4 m = make_float4(fmaxf(fmaxf(m0.x, m1.x), fmaxf(m2.x, m3.x)),
                           fmaxf(fmaxf(m0.y, m1.y), fmaxf(m2.y, m3.y)),
                           fmaxf(fmaxf(m0.z, m1.z), fmaxf(m2.z, m3.z)),
                           fmaxf(fmaxf(m0.w, m1.w), fmaxf(m2.w, m3.w)));
    if (end == start) m = make_float4(0.f, 0.f, 0.f, 0.f);  // empty segment -> 0

    size_t o = (size_t)warp * D + lane * 4;
    *reinterpret_cast<float4*>(g_sum + o) = s;
    *reinterpret_cast<float4*>(g_max + o) = m;
}

// ---------------- 6. per-block BN partial sums (deterministic) ------------
__global__ void k_stats(const float* __restrict__ h, const float* __restrict__ hin) {
    int d   = threadIdx.x;           // 0..127
    int blk = blockIdx.x;            // 0..STAT_BLOCKS-1
    const int chunk = (N_NODES + STAT_BLOCKS - 1) / STAT_BLOCKS;  // 125
    int n0 = blk * chunk;
    int n1 = min(N_NODES, n0 + chunk);

    float s[N_OPS] = {0, 0, 0, 0, 0};
    float q[N_OPS] = {0, 0, 0, 0, 0};
    for (int n = n0; n < n1; n++) {
        size_t o = (size_t)n * D + d;
        float x0 = h[o];
        float x1 = hin[o];
        float x2 = g_sum[o];
        float inv = 1.0f / fmaxf((float)g_deg[n], 1.0f);
        float x3 = x2 * inv;
        float x4 = g_max[o];
        s[0] += x0; q[0] += x0 * x0;
        s[1] += x1; q[1] += x1 * x1;
        s[2] += x2; q[2] += x2 * x2;
        s[3] += x3; q[3] += x3 * x3;
        s[4] += x4; q[4] += x4 * x4;
    }
    size_t base = (size_t)blk * 2 * N_OPS * D;
    #pragma unroll
    for (int b = 0; b < N_OPS; b++) {
        g_part[base + b * D + d]           = s[b];
        g_part[base + (N_OPS + b) * D + d] = q[b];
    }
}

// ---------------- 7. reduce partials -> fused BN coefficients -------------
__global__ void k_coef(const float* __restrict__ w,
                       const float* __restrict__ gamma,
                       const float* __restrict__ beta) {
    int t = blockIdx.x * blockDim.x + threadIdx.x;  // (b,d) flat
    if (t >= N_OPS * D) return;
    int b = t / D;
    float S = 0.f, Q = 0.f;
    for (int g = 0; g < STAT_BLOCKS; g++) {
        size_t base = (size_t)g * 2 * N_OPS * D;
        S += g_part[base + t];
        Q += g_part[base + N_OPS * D + t];
    }
    float mu   = S * (1.0f / N_NODES);
    float var  = fmaxf(Q * (1.0f / N_NODES) - mu * mu, 0.0f);
    float rstd = rsqrtf(var + EPS);
    float A = w[b] * gamma[t] * rstd;   // weights >= 0, fold inside ReLU
    float C = w[b] * beta[t] - A * mu;
    g_A[t] = A;
    g_C[t] = C;
}

// ---------------- 8. fused normalize + ReLU + weighted sum ----------------
__global__ void k_final(const float* __restrict__ h, const float* __restrict__ hin,
                        float* __restrict__ out) {
    __shared__ float sA[N_OPS * D];
    __shared__ float sC[N_OPS * D];
    for (int i = threadIdx.x; i < N_OPS * D; i += blockDim.x) {
        sA[i] = g_A[i];
        sC[i] = g_C[i];
    }
    __syncthreads();

    int gid = blockIdx.x * blockDim.x + threadIdx.x;  // one float4 per thread
    if (gid >= N_NODES * (D / 4)) return;
    int n  = gid >> 5;
    int f4 = (gid & 31) * 4;
    size_t o = (size_t)n * D + f4;

    float4 x0 = *reinterpret_cast<const float4*>(h + o);
    float4 x1 = *reinterpret_cast<const float4*>(hin + o);
    float4 x2 = *reinterpret_cast<const float4*>(g_sum + o);
    float4 x4 = *reinterpret_cast<const float4*>(g_max + o);
    float inv = 1.0f / fmaxf((float)g_deg[n], 1.0f);
    float4 x3 = make_float4(x2.x * inv, x2.y * inv, x2.z * inv, x2.w * inv);

    float xs[N_OPS][4] = {
        {x0.x, x0.y, x0.z, x0.w},
        {x1.x, x1.y, x1.z, x1.w},
        {x2.x, x2.y, x2.z, x2.w},
        {x3.x, x3.y, x3.z, x3.w},
        {x4.x, x4.y, x4.z, x4.w},
    };
    float acc[4] = {0.f, 0.f, 0.f, 0.f};
    #pragma unroll
    for (int b = 0; b < N_OPS; b++) {
        #pragma unroll
        for (int c = 0; c < 4; c++) {
            float A = sA[b * D + f4 + c];
            float C = sC[b * D + f4 + c];
            acc[c] += fmaxf(fmaf(A, xs[b][c], C), 0.0f);
        }
    }
    *reinterpret_cast<float4*>(out + o) = make_float4(acc[0], acc[1], acc[2], acc[3]);
}

// ---------------- launch ---------------------------------------------------
extern "C" void kernel_launch(void* const* d_in, const int* in_sizes, int n_in,
                              void* d_out, int out_size) {
    const float* weights = (const float*)d_in[0];
    const void*  ei      = d_in[1];                 // int32 or int64, detected on-device
    const float* h       = (const float*)d_in[2];
    const float* hin     = (const float*)d_in[3];
    const float* gamma   = (const float*)d_in[4];
    const float* beta    = (const float*)d_in[5];
    float*       out     = (float*)d_out;

    k_detect<<<1, 32>>>((const long long*)ei);
    k_zero_deg<<<(N_NODES + 255) / 256, 256>>>();
    k_hist<<<(N_EDGES + 255) / 256, 256>>>(ei);
    k_chunksum<<<SCAN_BLOCKS, 256>>>();
    k_bscan<<<1, 64>>>();
    k_apply<<<SCAN_BLOCKS, 256>>>();
    k_fill<<<(N_EDGES + 255) / 256, 256>>>(ei);
    k_agg<<<(N_NODES * 32 + 255) / 256, 256>>>(h);
    k_stats<<<STAT_BLOCKS, D>>>(h, hin);
    k_coef<<<(N_OPS * D + 255) / 256, 256>>>(weights, gamma, beta);
    k_final<<<(N_NODES * (D / 4) + 255) / 256, 256>>>(h, hin, out);
}